// round 1
// baseline (speedup 1.0000x reference)
#include <cuda_runtime.h>
#include <cuda_bf16.h>
#include <cstdint>

#define BB 32
#define DD 128
#define LC 2048
#define LQ 512
#define NEG (-1e30f)

// Scratch (device globals: allocation-free per harness rules)
__device__ float g_S[(size_t)BB*LC*LQ];     // 134 MB logits
__device__ float g_T[(size_t)BB*LQ*DD];     // S2^T @ Ct
__device__ float g_sub0[BB*LC];
__device__ float g_sub1[BB*LQ];
__device__ float g_rmax[BB*LC];
__device__ float g_rsum[BB*LC];
__device__ float g_cmax[BB*LQ];
__device__ float g_csum[BB*LQ];

// ---------------- sub0 / sub1 ----------------
__global__ void k_sub0(const float* __restrict__ C, const float* __restrict__ w) {
    int b = blockIdx.y;
    int c = blockIdx.x * 256 + threadIdx.x;
    const float* Cb = C + (size_t)b * DD * LC;
    float acc = 0.f;
#pragma unroll 8
    for (int d = 0; d < DD; d++) acc += Cb[(size_t)d * LC + c] * w[d];
    g_sub0[b * LC + c] = acc;
}

__global__ void k_sub1(const float* __restrict__ Q, const float* __restrict__ w) {
    int b = blockIdx.y;
    int q = blockIdx.x * 256 + threadIdx.x;
    const float* Qb = Q + (size_t)b * DD * LQ;
    float acc = 0.f;
#pragma unroll 8
    for (int d = 0; d < DD; d++) acc += Qb[(size_t)d * LQ + q] * w[d];
    g_sub1[b * LQ + q] = acc;
}

// ---------------- GEMM S: S[c][q] = sum_d C[d][c]*w[d]*Q[d][q] + sub0 + sub1 + bias
__global__ __launch_bounds__(256) void k_gemm_S(
    const float* __restrict__ C, const float* __restrict__ Q,
    const float* __restrict__ w4mlu, const float* __restrict__ bias) {
    __shared__ float As[16][64];  // [k=d][m=c]
    __shared__ float Bs[16][64];  // [k=d][n=q]
    int b = blockIdx.z;
    int m0 = blockIdx.y * 64;  // c
    int n0 = blockIdx.x * 64;  // q
    int tid = threadIdx.x;
    int tx = tid & 15, ty = tid >> 4;
    const float* Cb = C + (size_t)b * DD * LC + m0;
    const float* Qb = Q + (size_t)b * DD * LQ + n0;
    float acc[4][4] = {};
    for (int k0 = 0; k0 < DD; k0 += 16) {
        int r = tid >> 4, cc = (tid & 15) * 4;
        float4 v = *(const float4*)(Cb + (size_t)(k0 + r) * LC + cc);
        float w = w4mlu[k0 + r];
        As[r][cc] = v.x * w; As[r][cc + 1] = v.y * w;
        As[r][cc + 2] = v.z * w; As[r][cc + 3] = v.w * w;
        float4 u = *(const float4*)(Qb + (size_t)(k0 + r) * LQ + cc);
        Bs[r][cc] = u.x; Bs[r][cc + 1] = u.y; Bs[r][cc + 2] = u.z; Bs[r][cc + 3] = u.w;
        __syncthreads();
#pragma unroll
        for (int k = 0; k < 16; k++) {
            float4 a = *(float4*)&As[k][ty * 4];
            float4 bq = *(float4*)&Bs[k][tx * 4];
            acc[0][0] += a.x * bq.x; acc[0][1] += a.x * bq.y; acc[0][2] += a.x * bq.z; acc[0][3] += a.x * bq.w;
            acc[1][0] += a.y * bq.x; acc[1][1] += a.y * bq.y; acc[1][2] += a.y * bq.z; acc[1][3] += a.y * bq.w;
            acc[2][0] += a.z * bq.x; acc[2][1] += a.z * bq.y; acc[2][2] += a.z * bq.z; acc[2][3] += a.z * bq.w;
            acc[3][0] += a.w * bq.x; acc[3][1] += a.w * bq.y; acc[3][2] += a.w * bq.z; acc[3][3] += a.w * bq.w;
        }
        __syncthreads();
    }
    float bb = bias[0];
    float s1[4];
#pragma unroll
    for (int j = 0; j < 4; j++) s1[j] = g_sub1[b * LQ + n0 + tx * 4 + j];
#pragma unroll
    for (int i = 0; i < 4; i++) {
        int c = m0 + ty * 4 + i;
        float s0 = g_sub0[b * LC + c] + bb;
        float4 o;
        o.x = acc[i][0] + s0 + s1[0];
        o.y = acc[i][1] + s0 + s1[1];
        o.z = acc[i][2] + s0 + s1[2];
        o.w = acc[i][3] + s0 + s1[3];
        *(float4*)&g_S[((size_t)(b * LC + c)) * LQ + n0 + tx * 4] = o;
    }
}

// ---------------- row softmax stats (over q, masked by Qmask) ----------------
__global__ void k_rowstats(const float* __restrict__ Qmask) {
    int warp = threadIdx.x >> 5, lane = threadIdx.x & 31;
    int row = blockIdx.x * 8 + warp;   // in [0, B*LC)
    int b = row / LC;
    const float* Srow = g_S + (size_t)row * LQ;
    const float* Qm = Qmask + b * LQ;
    float vals[16];
    float m = -1e38f;
#pragma unroll
    for (int i = 0; i < 16; i++) {
        int q = lane + i * 32;
        float s = Srow[q];
        float msk = Qm[q];
        float l = s * msk + (1.f - msk) * NEG;
        vals[i] = l;
        m = fmaxf(m, l);
    }
#pragma unroll
    for (int o = 16; o; o >>= 1) m = fmaxf(m, __shfl_xor_sync(~0u, m, o));
    float sum = 0.f;
#pragma unroll
    for (int i = 0; i < 16; i++) sum += __expf(vals[i] - m);
#pragma unroll
    for (int o = 16; o; o >>= 1) sum += __shfl_xor_sync(~0u, sum, o);
    if (lane == 0) { g_rmax[row] = m; g_rsum[row] = sum; }
}

// ---------------- col softmax stats (over c, masked by Cmask) ----------------
__global__ void k_colstats(const float* __restrict__ Cmask) {
    __shared__ float sm[8][32], ss[8][32];
    int b = blockIdx.y;
    int q0 = blockIdx.x * 32;
    int qi = threadIdx.x & 31, cj = threadIdx.x >> 5;
    int q = q0 + qi;
    const float* Sb = g_S + (size_t)b * LC * LQ;
    const float* Cm = Cmask + b * LC;
    float m = -1e38f, s = 0.f;
    for (int c = cj; c < LC; c += 8) {
        float v = Sb[(size_t)c * LQ + q];
        float msk = Cm[c];
        float l = v * msk + (1.f - msk) * NEG;
        float nm = fmaxf(m, l);
        s = s * __expf(m - nm) + __expf(l - nm);
        m = nm;
    }
    sm[cj][qi] = m; ss[cj][qi] = s;
    __syncthreads();
    if (cj == 0) {
        float M = sm[0][qi], S = ss[0][qi];
#pragma unroll
        for (int j = 1; j < 8; j++) {
            float m2 = sm[j][qi], s2 = ss[j][qi];
            float nm = fmaxf(M, m2);
            S = S * __expf(M - nm) + s2 * __expf(m2 - nm);
            M = nm;
        }
        g_cmax[b * LQ + q] = M;
        g_csum[b * LQ + q] = S;
    }
}

// ---------------- GEMM T: T[q][d] = (1/csum[q]) * sum_c exp(masked(S)-cmax[q]) * C[d][c]
__global__ __launch_bounds__(256) void k_gemm_T(
    const float* __restrict__ C, const float* __restrict__ Cmask) {
    __shared__ float As[32][64];    // p2[k=c][m=q]
    __shared__ float Bs[32][132];   // Ct[k=c][n=d] (padded)
    __shared__ float s_cmax[64], s_csum[64];
    int b = blockIdx.y;
    int m0 = blockIdx.x * 64;  // q tile
    int tid = threadIdx.x;
    int tx = tid & 15, ty = tid >> 4;
    if (tid < 64) {
        s_cmax[tid] = g_cmax[b * LQ + m0 + tid];
        s_csum[tid] = g_csum[b * LQ + m0 + tid];
    }
    __syncthreads();
    const float* Sb = g_S + (size_t)b * LC * LQ;
    const float* Cb = C + (size_t)b * DD * LC;
    const float* Cm = Cmask + b * LC;
    float acc[4][8] = {};
    for (int k0 = 0; k0 < LC; k0 += 32) {
        {   // A tile: 32 c-rows x 64 q, with fused exp
            int r = tid >> 3, col = (tid & 7) * 8;
            float cm = Cm[k0 + r];
            float ng = (1.f - cm) * NEG;
            const float* src = Sb + (size_t)(k0 + r) * LQ + m0 + col;
            float4 v0 = *(const float4*)src;
            float4 v1 = *(const float4*)(src + 4);
            As[r][col + 0] = __expf(v0.x * cm + ng - s_cmax[col + 0]);
            As[r][col + 1] = __expf(v0.y * cm + ng - s_cmax[col + 1]);
            As[r][col + 2] = __expf(v0.z * cm + ng - s_cmax[col + 2]);
            As[r][col + 3] = __expf(v0.w * cm + ng - s_cmax[col + 3]);
            As[r][col + 4] = __expf(v1.x * cm + ng - s_cmax[col + 4]);
            As[r][col + 5] = __expf(v1.y * cm + ng - s_cmax[col + 5]);
            As[r][col + 6] = __expf(v1.z * cm + ng - s_cmax[col + 6]);
            As[r][col + 7] = __expf(v1.w * cm + ng - s_cmax[col + 7]);
        }
        {   // B tile: transpose-load C[d][c] -> Bs[c][d]
            int cc = (tid & 7) * 4;
            int d = tid >> 3;
#pragma unroll
            for (int dd = 0; dd < 4; dd++) {
                float4 v = *(const float4*)(Cb + (size_t)(d + dd * 32) * LC + k0 + cc);
                Bs[cc + 0][d + dd * 32] = v.x;
                Bs[cc + 1][d + dd * 32] = v.y;
                Bs[cc + 2][d + dd * 32] = v.z;
                Bs[cc + 3][d + dd * 32] = v.w;
            }
        }
        __syncthreads();
#pragma unroll 8
        for (int k = 0; k < 32; k++) {
            float4 a = *(float4*)&As[k][ty * 4];
            float4 b0 = *(float4*)&Bs[k][tx * 8];
            float4 b1 = *(float4*)&Bs[k][tx * 8 + 4];
            float av[4] = {a.x, a.y, a.z, a.w};
            float bv[8] = {b0.x, b0.y, b0.z, b0.w, b1.x, b1.y, b1.z, b1.w};
#pragma unroll
            for (int i = 0; i < 4; i++)
#pragma unroll
                for (int j = 0; j < 8; j++) acc[i][j] += av[i] * bv[j];
        }
        __syncthreads();
    }
#pragma unroll
    for (int i = 0; i < 4; i++) {
        int q = m0 + ty * 4 + i;
        float inv = 1.f / s_csum[ty * 4 + i];
        float* dst = &g_T[((size_t)(b * LQ + q)) * DD + tx * 8];
        float4 o0 = {acc[i][0] * inv, acc[i][1] * inv, acc[i][2] * inv, acc[i][3] * inv};
        float4 o1 = {acc[i][4] * inv, acc[i][5] * inv, acc[i][6] * inv, acc[i][7] * inv};
        *(float4*)dst = o0;
        *(float4*)(dst + 4) = o1;
    }
}

// ---------------- GEMM F: A = S1@Qt, Bm = S1@T, fused epilogue writes out ----
__global__ __launch_bounds__(256) void k_gemm_F(
    const float* __restrict__ C, const float* __restrict__ Q,
    const float* __restrict__ Qmask, float* __restrict__ out) {
    __shared__ float As[32][64];    // p1 (unnormalized) [k=q][m=c]
    __shared__ float BQ[32][128];   // Qt [k=q][n=d]
    __shared__ float BT[32][128];   // T  [k=q][n=d]
    __shared__ float s_rmax[64], s_rsum[64];
    int b = blockIdx.y;
    int m0 = blockIdx.x * 64;  // c tile
    int tid = threadIdx.x;
    int tx = tid & 15, ty = tid >> 4;
    if (tid < 64) {
        s_rmax[tid] = g_rmax[b * LC + m0 + tid];
        s_rsum[tid] = g_rsum[b * LC + m0 + tid];
    }
    __syncthreads();
    const float* Sb = g_S + (size_t)b * LC * LQ;
    const float* Qb = Q + (size_t)b * DD * LQ;
    const float* Tb = g_T + (size_t)b * LQ * DD;
    const float* Qm = Qmask + b * LQ;
    float accA[4][8] = {}, accB[4][8] = {};
    for (int k0 = 0; k0 < LQ; k0 += 32) {
        {   // A tile: 64 c-rows x 32 q, fused exp, stored transposed
            int m = tid >> 2, kc = (tid & 3) * 8;
            float rmx = s_rmax[m];
            const float* src = Sb + (size_t)(m0 + m) * LQ + k0 + kc;
            float4 v0 = *(const float4*)src;
            float4 v1 = *(const float4*)(src + 4);
            float vv[8] = {v0.x, v0.y, v0.z, v0.w, v1.x, v1.y, v1.z, v1.w};
#pragma unroll
            for (int ii = 0; ii < 8; ii++) {
                float msk = Qm[k0 + kc + ii];
                float l = vv[ii] * msk + (1.f - msk) * NEG;
                As[kc + ii][m] = __expf(l - rmx);
            }
        }
        {   // BQ: transpose-load Q[d][q] -> BQ[q][d]
            int cc = (tid & 7) * 4;
            int d = tid >> 3;
#pragma unroll
            for (int dd = 0; dd < 4; dd++) {
                float4 v = *(const float4*)(Qb + (size_t)(d + dd * 32) * LQ + k0 + cc);
                BQ[cc + 0][d + dd * 32] = v.x;
                BQ[cc + 1][d + dd * 32] = v.y;
                BQ[cc + 2][d + dd * 32] = v.z;
                BQ[cc + 3][d + dd * 32] = v.w;
            }
        }
        {   // BT: direct load T
            int r = tid >> 3, cc = (tid & 7) * 16;
            const float* src = Tb + (size_t)(k0 + r) * DD + cc;
#pragma unroll
            for (int u = 0; u < 4; u++) {
                float4 v = *(const float4*)(src + u * 4);
                *(float4*)&BT[r][cc + u * 4] = v;
            }
        }
        __syncthreads();
#pragma unroll 4
        for (int k = 0; k < 32; k++) {
            float4 a = *(float4*)&As[k][ty * 4];
            float4 q0 = *(float4*)&BQ[k][tx * 8];
            float4 q1 = *(float4*)&BQ[k][tx * 8 + 4];
            float4 t0 = *(float4*)&BT[k][tx * 8];
            float4 t1 = *(float4*)&BT[k][tx * 8 + 4];
            float av[4] = {a.x, a.y, a.z, a.w};
            float qv[8] = {q0.x, q0.y, q0.z, q0.w, q1.x, q1.y, q1.z, q1.w};
            float tv[8] = {t0.x, t0.y, t0.z, t0.w, t1.x, t1.y, t1.z, t1.w};
#pragma unroll
            for (int i = 0; i < 4; i++)
#pragma unroll
                for (int j = 0; j < 8; j++) {
                    accA[i][j] += av[i] * qv[j];
                    accB[i][j] += av[i] * tv[j];
                }
        }
        __syncthreads();
    }
    // epilogue: out[b][od][c], od in {d, 128+d, 256+d, 384+d}
    float inv[4];
#pragma unroll
    for (int i = 0; i < 4; i++) inv[i] = 1.f / s_rsum[ty * 4 + i];
    int cbase = m0 + ty * 4;
    size_t ob = ((size_t)b * 512) * 2048 + cbase;
#pragma unroll
    for (int j = 0; j < 8; j++) {
        int d = tx * 8 + j;
        float4 cv = *(const float4*)(C + ((size_t)b * DD + d) * LC + cbase);
        float4 av = {accA[0][j] * inv[0], accA[1][j] * inv[1],
                     accA[2][j] * inv[2], accA[3][j] * inv[3]};
        float4 bv = {accB[0][j] * inv[0], accB[1][j] * inv[1],
                     accB[2][j] * inv[2], accB[3][j] * inv[3]};
        float4 ca = {cv.x * av.x, cv.y * av.y, cv.z * av.z, cv.w * av.w};
        float4 cb = {cv.x * bv.x, cv.y * bv.y, cv.z * bv.z, cv.w * bv.w};
        *(float4*)&out[ob + (size_t)d * 2048] = cv;
        *(float4*)&out[ob + (size_t)(128 + d) * 2048] = av;
        *(float4*)&out[ob + (size_t)(256 + d) * 2048] = ca;
        *(float4*)&out[ob + (size_t)(384 + d) * 2048] = cb;
    }
}

extern "C" void kernel_launch(void* const* d_in, const int* in_sizes, int n_in,
                              void* d_out, int out_size) {
    (void)in_sizes; (void)n_in; (void)out_size;
    const float* C     = (const float*)d_in[0];
    const float* Q     = (const float*)d_in[1];
    const float* Cmask = (const float*)d_in[2];
    const float* Qmask = (const float*)d_in[3];
    const float* w4C   = (const float*)d_in[4];
    const float* w4Q   = (const float*)d_in[5];
    const float* w4mlu = (const float*)d_in[6];
    const float* bias  = (const float*)d_in[7];
    float* out = (float*)d_out;

    k_sub0<<<dim3(LC / 256, BB), 256>>>(C, w4C);
    k_sub1<<<dim3(LQ / 256, BB), 256>>>(Q, w4Q);
    k_gemm_S<<<dim3(LQ / 64, LC / 64, BB), 256>>>(C, Q, w4mlu, bias);
    k_rowstats<<<BB * LC / 8, 256>>>(Qmask);
    k_colstats<<<dim3(LQ / 32, BB), 256>>>(Cmask);
    k_gemm_T<<<dim3(LQ / 64, BB), 256>>>(C, Cmask);
    k_gemm_F<<<dim3(LC / 64, BB), 256>>>(C, Q, Qmask, out);
}